// round 1
// baseline (speedup 1.0000x reference)
#include <cuda_runtime.h>
#include <math.h>

#define HH   16
#define TT   2048
#define DD   192     // NOPE + ROPE
#define NOPE 128
#define ROPE 64
#define LORA 512
#define DV   128

// Scratch (allocation-free rule: __device__ globals)
__device__ float g_kcat[HH * TT * DD];   // [h][t][192]  (k_nope ++ k_pe)
__device__ float g_v[HH * TT * DV];      // [h][t][128]  (k_c @ w_uv[h])

// ---------------------------------------------------------------------------
// prep GEMM: per (64-row tile, head) computes C(64x128) = A(64x512) * B(512x128)
// mode 0: B = w_kv_b[:, h*256 .. h*256+128) -> g_kcat[...][0:128], also fills
//         g_kcat[...][128:192] with broadcast k_pe
// mode 1: B = w_uv[h]                       -> g_v
// ---------------------------------------------------------------------------
__global__ __launch_bounds__(256) void prep_gemm(
    const float* __restrict__ A,       // k_c (T x LORA)
    const float* __restrict__ Wkvb,    // (LORA x H*256)
    const float* __restrict__ Wuv,     // (H x LORA x 128)
    const float* __restrict__ kpe,     // (T x 64)
    int mode)
{
    __shared__ float As[64 * 17];      // padded stride 17 (bank-conflict-free a reads)
    __shared__ float Bs[16 * 128];

    const int h  = blockIdx.y;
    const int mt = blockIdx.x;
    const int tid = threadIdx.x;
    const int ty = tid >> 4, tx = tid & 15;

    const float* B;
    int ldb, ldc;
    float* C;
    if (mode == 0) {
        B = Wkvb + h * 256;            ldb = HH * 256;   // 4096
        C = g_kcat + (h * TT + mt * 64) * DD;  ldc = DD;
    } else {
        B = Wuv + h * (LORA * DV);     ldb = DV;
        C = g_v + (h * TT + mt * 64) * DV;     ldc = DV;
    }
    const float* Ablk = A + (mt * 64) * LORA;

    float acc[4][8];
    #pragma unroll
    for (int i = 0; i < 4; i++)
        #pragma unroll
        for (int j = 0; j < 8; j++) acc[i][j] = 0.f;

    for (int k0 = 0; k0 < LORA; k0 += 16) {
        // A chunk 64x16 (one float4 per thread)
        {
            int r = tid >> 2, c0 = (tid & 3) * 4;
            float4 av = *(const float4*)(Ablk + r * LORA + k0 + c0);
            As[r * 17 + c0 + 0] = av.x;
            As[r * 17 + c0 + 1] = av.y;
            As[r * 17 + c0 + 2] = av.z;
            As[r * 17 + c0 + 3] = av.w;
        }
        // B chunk 16x128 (512 float4, 2 per thread)
        #pragma unroll
        for (int it = 0; it < 2; it++) {
            int idx = tid + it * 256;
            int r = idx >> 5, c4 = idx & 31;
            *(float4*)(Bs + r * 128 + c4 * 4) =
                *(const float4*)(B + (k0 + r) * ldb + c4 * 4);
        }
        __syncthreads();
        #pragma unroll
        for (int kk = 0; kk < 16; kk++) {
            float a[4];
            #pragma unroll
            for (int i = 0; i < 4; i++) a[i] = As[(ty * 4 + i) * 17 + kk];
            float4 b0 = *(const float4*)(Bs + kk * 128 + tx * 8);
            float4 b1 = *(const float4*)(Bs + kk * 128 + tx * 8 + 4);
            #pragma unroll
            for (int i = 0; i < 4; i++) {
                acc[i][0] += a[i] * b0.x; acc[i][1] += a[i] * b0.y;
                acc[i][2] += a[i] * b0.z; acc[i][3] += a[i] * b0.w;
                acc[i][4] += a[i] * b1.x; acc[i][5] += a[i] * b1.y;
                acc[i][6] += a[i] * b1.z; acc[i][7] += a[i] * b1.w;
            }
        }
        __syncthreads();
    }
    #pragma unroll
    for (int i = 0; i < 4; i++) {
        int r = ty * 4 + i;
        *(float4*)(C + r * ldc + tx * 8) =
            make_float4(acc[i][0], acc[i][1], acc[i][2], acc[i][3]);
        *(float4*)(C + r * ldc + tx * 8 + 4) =
            make_float4(acc[i][4], acc[i][5], acc[i][6], acc[i][7]);
    }
    if (mode == 0) {
        // broadcast k_pe into cols [128,192): 64 rows x 16 float4
        #pragma unroll
        for (int it = 0; it < 4; it++) {
            int idx = tid + it * 256;
            int r = idx >> 4, c4 = idx & 15;
            *(float4*)(C + r * DD + NOPE + c4 * 4) =
                *(const float4*)(kpe + (mt * 64 + r) * ROPE + c4 * 4);
        }
    }
}

// ---------------------------------------------------------------------------
// Causal flash attention: one block per (q-tile of 64, head).
// 256 threads as 16x16 grid: thread owns 4 q-rows x 4 k-cols of S,
// and 4 q-rows x 8 v-cols of O.
// ---------------------------------------------------------------------------
__global__ __launch_bounds__(256) void flash_kernel(
    const float* __restrict__ q, float* __restrict__ out)
{
    extern __shared__ float sm[];
    float* Qs = sm;                    // [64][196]
    float* Ks = sm + 64 * 196;         // [64][196]
    float* Vs = Ks + 64 * 196;         // [64][132]
    float* Ps = Vs + 64 * 132;         // [64][68]

    const int h  = blockIdx.y;
    const int qt = (int)gridDim.x - 1 - (int)blockIdx.x;  // big tiles first
    const int tid = threadIdx.x;
    const int ty = tid >> 4, tx = tid & 15;
    const float SCALE = 0.07216878364870323f;   // 1/sqrt(192)

    // Q tile 64x192 (pre-scaled): 3072 float4, 12 per thread
    #pragma unroll
    for (int it = 0; it < 12; it++) {
        int idx = tid + it * 256;
        int r = idx / 48, c4 = idx % 48;
        float4 v = *(const float4*)(q + ((qt * 64 + r) * HH + h) * DD + c4 * 4);
        v.x *= SCALE; v.y *= SCALE; v.z *= SCALE; v.w *= SCALE;
        *(float4*)(Qs + r * 196 + c4 * 4) = v;
    }

    float m[4], l[4], O[4][8];
    #pragma unroll
    for (int i = 0; i < 4; i++) {
        m[i] = -1e30f; l[i] = 0.f;
        #pragma unroll
        for (int j = 0; j < 8; j++) O[i][j] = 0.f;
    }

    const float* kbase = g_kcat + h * TT * DD;
    const float* vbase = g_v + h * TT * DV;

    for (int kt = 0; kt <= qt; kt++) {
        __syncthreads();   // protect Ks/Vs/Ps reuse from previous iteration
        #pragma unroll
        for (int it = 0; it < 12; it++) {
            int idx = tid + it * 256;
            int r = idx / 48, c4 = idx % 48;
            *(float4*)(Ks + r * 196 + c4 * 4) =
                *(const float4*)(kbase + (kt * 64 + r) * DD + c4 * 4);
        }
        #pragma unroll
        for (int it = 0; it < 8; it++) {
            int idx = tid + it * 256;
            int r = idx >> 5, c4 = idx & 31;
            *(float4*)(Vs + r * 132 + c4 * 4) =
                *(const float4*)(vbase + (kt * 64 + r) * DV + c4 * 4);
        }
        __syncthreads();

        // ---- S = Q K^T (4x4 per thread) ----
        float s[4][4];
        #pragma unroll
        for (int i = 0; i < 4; i++)
            #pragma unroll
            for (int j = 0; j < 4; j++) s[i][j] = 0.f;

        #pragma unroll 4
        for (int d = 0; d < DD; d += 4) {
            float4 a[4], b[4];
            #pragma unroll
            for (int i = 0; i < 4; i++)
                a[i] = *(const float4*)(Qs + (ty * 4 + i) * 196 + d);
            #pragma unroll
            for (int j = 0; j < 4; j++)
                b[j] = *(const float4*)(Ks + (tx * 4 + j) * 196 + d);
            #pragma unroll
            for (int i = 0; i < 4; i++)
                #pragma unroll
                for (int j = 0; j < 4; j++)
                    s[i][j] += a[i].x * b[j].x + a[i].y * b[j].y
                             + a[i].z * b[j].z + a[i].w * b[j].w;
        }

        // causal mask on diagonal tile
        if (kt == qt) {
            #pragma unroll
            for (int i = 0; i < 4; i++)
                #pragma unroll
                for (int j = 0; j < 4; j++)
                    if (tx * 4 + j > ty * 4 + i) s[i][j] = -1e30f;
        }

        // ---- online softmax ----
        float mt_[4];
        #pragma unroll
        for (int i = 0; i < 4; i++) {
            mt_[i] = fmaxf(fmaxf(s[i][0], s[i][1]), fmaxf(s[i][2], s[i][3]));
            #pragma unroll
            for (int off = 8; off > 0; off >>= 1)
                mt_[i] = fmaxf(mt_[i], __shfl_xor_sync(0xffffffffu, mt_[i], off));
        }
        #pragma unroll
        for (int i = 0; i < 4; i++) {
            float mn = fmaxf(m[i], mt_[i]);
            float alpha = __expf(m[i] - mn);
            m[i] = mn;
            float lt = 0.f;
            #pragma unroll
            for (int j = 0; j < 4; j++) {
                float p = __expf(s[i][j] - mn);
                Ps[(ty * 4 + i) * 68 + tx * 4 + j] = p;
                lt += p;
            }
            #pragma unroll
            for (int off = 8; off > 0; off >>= 1)
                lt += __shfl_xor_sync(0xffffffffu, lt, off);
            l[i] = l[i] * alpha + lt;
            #pragma unroll
            for (int j = 0; j < 8; j++) O[i][j] *= alpha;
        }
        __syncthreads();

        // ---- O += P V ----
        #pragma unroll 4
        for (int c = 0; c < 64; c++) {
            float4 v0 = *(const float4*)(Vs + c * 132 + tx * 8);
            float4 v1 = *(const float4*)(Vs + c * 132 + tx * 8 + 4);
            #pragma unroll
            for (int i = 0; i < 4; i++) {
                float p = Ps[(ty * 4 + i) * 68 + c];
                O[i][0] += p * v0.x; O[i][1] += p * v0.y;
                O[i][2] += p * v0.z; O[i][3] += p * v0.w;
                O[i][4] += p * v1.x; O[i][5] += p * v1.y;
                O[i][6] += p * v1.z; O[i][7] += p * v1.w;
            }
        }
    }

    // ---- epilogue: out[t][h*128 + v] = O / l ----
    #pragma unroll
    for (int i = 0; i < 4; i++) {
        float inv = 1.f / l[i];
        int gr = qt * 64 + ty * 4 + i;
        float* dst = out + gr * (HH * DV) + h * DV + tx * 8;
        *(float4*)(dst) =
            make_float4(O[i][0] * inv, O[i][1] * inv, O[i][2] * inv, O[i][3] * inv);
        *(float4*)(dst + 4) =
            make_float4(O[i][4] * inv, O[i][5] * inv, O[i][6] * inv, O[i][7] * inv);
    }
}

// ---------------------------------------------------------------------------
extern "C" void kernel_launch(void* const* d_in, const int* in_sizes, int n_in,
                              void* d_out, int out_size) {
    const float* q    = (const float*)d_in[0];   // (T, H, 192)
    const float* kc   = (const float*)d_in[1];   // (T, 512)
    const float* kpe  = (const float*)d_in[2];   // (T, 64)
    const float* wkvb = (const float*)d_in[3];   // (512, 4096)
    const float* wuv  = (const float*)d_in[4];   // (16, 512, 128)
    float* out = (float*)d_out;                  // (T, 2048)
    (void)in_sizes; (void)n_in; (void)out_size;

    const int FLASH_SMEM = (64 * 196 * 2 + 64 * 132 + 64 * 68) * 4;  // 151552 B
    cudaFuncSetAttribute(flash_kernel,
                         cudaFuncAttributeMaxDynamicSharedMemorySize, FLASH_SMEM);

    dim3 grid(TT / 64, HH);
    prep_gemm<<<grid, 256>>>(kc, wkvb, wuv, kpe, 0);
    prep_gemm<<<grid, 256>>>(kc, wkvb, wuv, kpe, 1);
    flash_kernel<<<grid, 256, FLASH_SMEM>>>(q, out);
}

// round 3
// speedup vs baseline: 4.0742x; 4.0742x over previous
#include <cuda_runtime.h>
#include <cuda_bf16.h>
#include <cstdint>

#define HH   16
#define TT   2048
#define DD   192
#define NOPE 128
#define ROPE 64
#define LORA 512
#define DV   128
#define QSCALE 0.07216878364870323f   // 1/sqrt(192)

// ---------------------------------------------------------------------------
// Device-global scratch (allocation-free rule)
// ---------------------------------------------------------------------------
__device__ __nv_bfloat16 g_kc_hi[TT * LORA],    g_kc_lo[TT * LORA];
__device__ __nv_bfloat16 g_q_hi [HH * TT * DD], g_q_lo [HH * TT * DD];
__device__ __nv_bfloat16 g_k_hi [HH * TT * DD], g_k_lo [HH * TT * DD];
__device__ __nv_bfloat16 g_vt_hi[HH * DV * TT], g_vt_lo[HH * DV * TT];
__device__ __nv_bfloat16 g_wbT_hi [HH * 128 * LORA], g_wbT_lo [HH * 128 * LORA];
__device__ __nv_bfloat16 g_wuvT_hi[HH * DV  * LORA], g_wuvT_lo[HH * DV  * LORA];

// ---------------------------------------------------------------------------
// HMMA m16n8k16 bf16 (row.col), fp32 accumulate
// ---------------------------------------------------------------------------
__device__ __forceinline__ void mma_bf16(float* c, const uint32_t* a, const uint32_t* b) {
    asm volatile(
        "mma.sync.aligned.m16n8k16.row.col.f32.bf16.bf16.f32 "
        "{%0,%1,%2,%3}, {%4,%5,%6,%7}, {%8,%9}, {%0,%1,%2,%3};"
        : "+f"(c[0]), "+f"(c[1]), "+f"(c[2]), "+f"(c[3])
        : "r"(a[0]), "r"(a[1]), "r"(a[2]), "r"(a[3]), "r"(b[0]), "r"(b[1]));
}

// ---------------------------------------------------------------------------
// Pre-split kernels (elementwise fp32 -> bf16 hi/lo)
// ---------------------------------------------------------------------------
__device__ __forceinline__ void split_store(__nv_bfloat16* dh, __nv_bfloat16* dl,
                                            int i, float x) {
    __nv_bfloat16 h = __float2bfloat16(x);
    dh[i] = h;
    dl[i] = __float2bfloat16(x - __bfloat162float(h));
}

__global__ void split_kc_k(const float* __restrict__ kc) {
    int i = blockIdx.x * 256 + threadIdx.x;
    split_store(g_kc_hi, g_kc_lo, i, kc[i]);
}
__global__ void split_q_k(const float* __restrict__ q) {
    int i = blockIdx.x * 256 + threadIdx.x;
    int d = i % DD, th = i / DD, t = th % TT, h = th / TT;
    split_store(g_q_hi, g_q_lo, i, q[(t * HH + h) * DD + d] * QSCALE);
}
__global__ void split_kpe_k(const float* __restrict__ kpe) {
    int i = blockIdx.x * 256 + threadIdx.x;
    int d = i % ROPE, th = i / ROPE, t = th % TT, h = th / TT;
    split_store(g_k_hi, g_k_lo, (h * TT + t) * DD + NOPE + d, kpe[t * ROPE + d]);
}
__global__ void split_wbT_k(const float* __restrict__ w) {
    int i = blockIdx.x * 256 + threadIdx.x;
    int k = i % LORA, nh = i / LORA, n = nh % 128, h = nh / 128;
    split_store(g_wbT_hi, g_wbT_lo, i, w[k * (HH * 256) + h * 256 + n]);
}
__global__ void split_wuvT_k(const float* __restrict__ w) {
    int i = blockIdx.x * 256 + threadIdx.x;
    int k = i % LORA, vh = i / LORA, v = vh % DV, h = vh / DV;
    split_store(g_wuvT_hi, g_wuvT_lo, i, w[(h * LORA + k) * DV + v]);
}

// ---------------------------------------------------------------------------
// prep: C(128x128) = A(128x512) * B(128x512)^T, bf16 3-pass, split out hi/lo
//   mode 0: A = kc rows (t), B = wkvb^T rows (n)  -> g_k[h][t][0:128]
//   mode 1: A = wuv^T rows (v), B = kc rows (t)   -> g_vt[h][v][t]
// 256 threads = 8 warps; warp tile 16 rows x 128 cols; K chunks of 64.
// ---------------------------------------------------------------------------
#define PSTR 72
#define PREP_SMEM (4 * 128 * PSTR * 2)    // 73728 B

__global__ __launch_bounds__(256, 1) void prep_mma(int mode) {
    extern __shared__ __nv_bfloat16 sp[];
    __nv_bfloat16* SAh = sp;
    __nv_bfloat16* SAl = sp + 128 * PSTR;
    __nv_bfloat16* SBh = sp + 2 * 128 * PSTR;
    __nv_bfloat16* SBl = sp + 3 * 128 * PSTR;

    const int tid = threadIdx.x, w = tid >> 5, lane = tid & 31;
    const int grp = lane >> 2, tig = lane & 3;
    const int h = blockIdx.x & 15, tt = blockIdx.x >> 4;
    const int r0 = w * 16 + grp;

    const __nv_bfloat16 *Ah, *Al, *Bh, *Bl;
    __nv_bfloat16 *D1, *D2;
    int dstride;
    if (mode == 0) {
        Ah = g_kc_hi + tt * 128 * LORA;  Al = g_kc_lo + tt * 128 * LORA;
        Bh = g_wbT_hi + h * 128 * LORA;  Bl = g_wbT_lo + h * 128 * LORA;
        D1 = g_k_hi + (h * TT + tt * 128) * DD;
        D2 = g_k_lo + (h * TT + tt * 128) * DD;
        dstride = DD;
    } else {
        Ah = g_wuvT_hi + h * DV * LORA;  Al = g_wuvT_lo + h * DV * LORA;
        Bh = g_kc_hi + tt * 128 * LORA;  Bl = g_kc_lo + tt * 128 * LORA;
        D1 = g_vt_hi + h * DV * TT + tt * 128;
        D2 = g_vt_lo + h * DV * TT + tt * 128;
        dstride = TT;
    }

    float cc[16][4];
    #pragma unroll
    for (int nt = 0; nt < 16; nt++)
        #pragma unroll
        for (int j = 0; j < 4; j++) cc[nt][j] = 0.f;

    for (int c = 0; c < 8; c++) {
        __syncthreads();
        #pragma unroll
        for (int it = 0; it < 4; it++) {
            int idx = tid + it * 256;
            int r = idx >> 3, c8 = (idx & 7) * 8;
            int so = r * PSTR + c8;
            int go = r * LORA + c * 64 + c8;
            *(uint4*)(SAh + so) = *(const uint4*)(Ah + go);
            *(uint4*)(SAl + so) = *(const uint4*)(Al + go);
            *(uint4*)(SBh + so) = *(const uint4*)(Bh + go);
            *(uint4*)(SBl + so) = *(const uint4*)(Bl + go);
        }
        __syncthreads();
        #pragma unroll
        for (int pass = 0; pass < 3; pass++) {
            const __nv_bfloat16* A = (pass == 2) ? SAl : SAh;
            const __nv_bfloat16* B = (pass == 1) ? SBl : SBh;
            #pragma unroll
            for (int ks = 0; ks < 4; ks++) {
                int ac = ks * 16 + 2 * tig;
                uint32_t a[4];
                a[0] = *(const uint32_t*)(A + r0 * PSTR + ac);
                a[1] = *(const uint32_t*)(A + (r0 + 8) * PSTR + ac);
                a[2] = *(const uint32_t*)(A + r0 * PSTR + ac + 8);
                a[3] = *(const uint32_t*)(A + (r0 + 8) * PSTR + ac + 8);
                #pragma unroll
                for (int nt = 0; nt < 16; nt++) {
                    uint32_t b[2];
                    const __nv_bfloat16* br = B + (nt * 8 + grp) * PSTR + ac;
                    b[0] = *(const uint32_t*)(br);
                    b[1] = *(const uint32_t*)(br + 8);
                    mma_bf16(cc[nt], a, b);
                }
            }
        }
    }

    // split-store C to hi/lo
    #pragma unroll
    for (int nt = 0; nt < 16; nt++) {
        int col = nt * 8 + 2 * tig;
        {
            __nv_bfloat162 hv = __floats2bfloat162_rn(cc[nt][0], cc[nt][1]);
            __nv_bfloat162 lv = __floats2bfloat162_rn(
                cc[nt][0] - __bfloat162float(hv.x),
                cc[nt][1] - __bfloat162float(hv.y));
            *(__nv_bfloat162*)(D1 + r0 * dstride + col) = hv;
            *(__nv_bfloat162*)(D2 + r0 * dstride + col) = lv;
        }
        {
            __nv_bfloat162 hv = __floats2bfloat162_rn(cc[nt][2], cc[nt][3]);
            __nv_bfloat162 lv = __floats2bfloat162_rn(
                cc[nt][2] - __bfloat162float(hv.x),
                cc[nt][3] - __bfloat162float(hv.y));
            *(__nv_bfloat162*)(D1 + (r0 + 8) * dstride + col) = hv;
            *(__nv_bfloat162*)(D2 + (r0 + 8) * dstride + col) = lv;
        }
    }
}

// ---------------------------------------------------------------------------
// Flash attention: 1 CTA per (128-row q tile, head). 256 threads = 8 warps,
// warp tile 16 q-rows x 128 cols. No-max softmax; O accumulates in registers.
// P converts from S-fragments to bf16 hi/lo A-fragments in-register.
// ---------------------------------------------------------------------------
#define QSTR 200
#define VSTR 136
#define FLASH_SMEM (4 * 128 * QSTR * 2)   // 204800 B

__global__ __launch_bounds__(256, 1) void flash_mma(float* __restrict__ out) {
    extern __shared__ __nv_bfloat16 sf[];
    __nv_bfloat16* Qh = sf;
    __nv_bfloat16* Ql = sf + 128 * QSTR;
    __nv_bfloat16* Kh = sf + 2 * 128 * QSTR;
    __nv_bfloat16* Kl = sf + 3 * 128 * QSTR;
    __nv_bfloat16* Vh = Kh;   // V overlays K region (stride VSTR)
    __nv_bfloat16* Vl = Kl;

    const int tid = threadIdx.x, w = tid >> 5, lane = tid & 31;
    const int grp = lane >> 2, tig = lane & 3;
    const int h = blockIdx.x & 15;
    const int qt = 15 - (blockIdx.x >> 4);   // heavy tiles first
    const int r0 = w * 16 + grp;             // local q row (and +8)

    // load Q tile (persistent)
    {
        const __nv_bfloat16* qh = g_q_hi + (h * TT + qt * 128) * DD;
        const __nv_bfloat16* ql = g_q_lo + (h * TT + qt * 128) * DD;
        #pragma unroll
        for (int it = 0; it < 12; it++) {
            int idx = tid + it * 256;
            int r = idx / 24, c8 = (idx % 24) * 8;
            *(uint4*)(Qh + r * QSTR + c8) = *(const uint4*)(qh + r * DD + c8);
            *(uint4*)(Ql + r * QSTR + c8) = *(const uint4*)(ql + r * DD + c8);
        }
    }

    const __nv_bfloat16* khb = g_k_hi + h * TT * DD;
    const __nv_bfloat16* klb = g_k_lo + h * TT * DD;
    const __nv_bfloat16* vhb = g_vt_hi + h * DV * TT;
    const __nv_bfloat16* vlb = g_vt_lo + h * DV * TT;

    float oc[16][4];
    #pragma unroll
    for (int nt = 0; nt < 16; nt++)
        #pragma unroll
        for (int j = 0; j < 4; j++) oc[nt][j] = 0.f;
    float ls0 = 0.f, ls1 = 0.f;

    for (int kt = 0; kt <= qt; kt++) {
        __syncthreads();   // prev PV done before K overwrite
        {
            const __nv_bfloat16* kh = khb + kt * 128 * DD;
            const __nv_bfloat16* kl = klb + kt * 128 * DD;
            #pragma unroll
            for (int it = 0; it < 12; it++) {
                int idx = tid + it * 256;
                int r = idx / 24, c8 = (idx % 24) * 8;
                *(uint4*)(Kh + r * QSTR + c8) = *(const uint4*)(kh + r * DD + c8);
                *(uint4*)(Kl + r * QSTR + c8) = *(const uint4*)(kl + r * DD + c8);
            }
        }
        __syncthreads();

        // ---- S = Q K^T (3-pass) ----
        float sc[16][4];
        #pragma unroll
        for (int nt = 0; nt < 16; nt++)
            #pragma unroll
            for (int j = 0; j < 4; j++) sc[nt][j] = 0.f;

        #pragma unroll
        for (int pass = 0; pass < 3; pass++) {
            const __nv_bfloat16* A = (pass == 2) ? Ql : Qh;
            const __nv_bfloat16* B = (pass == 1) ? Kl : Kh;
            #pragma unroll
            for (int ks = 0; ks < 12; ks++) {
                int ac = ks * 16 + 2 * tig;
                uint32_t a[4];
                a[0] = *(const uint32_t*)(A + r0 * QSTR + ac);
                a[1] = *(const uint32_t*)(A + (r0 + 8) * QSTR + ac);
                a[2] = *(const uint32_t*)(A + r0 * QSTR + ac + 8);
                a[3] = *(const uint32_t*)(A + (r0 + 8) * QSTR + ac + 8);
                #pragma unroll
                for (int nt = 0; nt < 16; nt++) {
                    uint32_t b[2];
                    const __nv_bfloat16* br = B + (nt * 8 + grp) * QSTR + ac;
                    b[0] = *(const uint32_t*)(br);
                    b[1] = *(const uint32_t*)(br + 8);
                    mma_bf16(sc[nt], a, b);
                }
            }
        }

        // ---- softmax (no max-sub) + in-register bf16 hi/lo split of P ----
        const bool diag = (kt == qt);
        uint32_t ph[8][4], pl[8][4];
        #pragma unroll
        for (int nt = 0; nt < 16; nt++) {
            int cb = nt * 8 + 2 * tig;
            float e0 = __expf(sc[nt][0]);
            float e1 = __expf(sc[nt][1]);
            float e2 = __expf(sc[nt][2]);
            float e3 = __expf(sc[nt][3]);
            if (diag) {
                if (cb     > r0)     e0 = 0.f;
                if (cb + 1 > r0)     e1 = 0.f;
                if (cb     > r0 + 8) e2 = 0.f;
                if (cb + 1 > r0 + 8) e3 = 0.f;
            }
            ls0 += e0 + e1;
            ls1 += e2 + e3;
            int g = nt >> 1, hf = (nt & 1) << 1;   // reg pair: 0,1 (low k8) / 2,3 (high k8)
            __nv_bfloat162 h01 = __floats2bfloat162_rn(e0, e1);
            __nv_bfloat162 l01 = __floats2bfloat162_rn(e0 - __bfloat162float(h01.x),
                                                       e1 - __bfloat162float(h01.y));
            __nv_bfloat162 h23 = __floats2bfloat162_rn(e2, e3);
            __nv_bfloat162 l23 = __floats2bfloat162_rn(e2 - __bfloat162float(h23.x),
                                                       e3 - __bfloat162float(h23.y));
            ph[g][hf]     = *(uint32_t*)&h01;
            ph[g][hf + 1] = *(uint32_t*)&h23;
            pl[g][hf]     = *(uint32_t*)&l01;
            pl[g][hf + 1] = *(uint32_t*)&l23;
        }

        __syncthreads();   // all warps done reading K before V overwrite
        {
            const __nv_bfloat16* vh = vhb + kt * 128;
            const __nv_bfloat16* vl = vlb + kt * 128;
            #pragma unroll
            for (int it = 0; it < 8; it++) {
                int idx = tid + it * 256;
                int r = idx >> 4, c8 = (idx & 15) * 8;
                *(uint4*)(Vh + r * VSTR + c8) = *(const uint4*)(vh + r * TT + c8);
                *(uint4*)(Vl + r * VSTR + c8) = *(const uint4*)(vl + r * TT + c8);
            }
        }
        __syncthreads();

        // ---- O += P V^T (3-pass: Ph*Vh, Ph*Vl, Pl*Vh) ----
        #pragma unroll
        for (int pass = 0; pass < 3; pass++) {
            const uint32_t (*Ap)[4] = (pass == 2) ? pl : ph;
            const __nv_bfloat16* B = (pass == 1) ? Vl : Vh;
            #pragma unroll
            for (int ks = 0; ks < 8; ks++) {
                int ac = ks * 16 + 2 * tig;
                #pragma unroll
                for (int nt = 0; nt < 16; nt++) {
                    uint32_t b[2];
                    const __nv_bfloat16* br = B + (nt * 8 + grp) * VSTR + ac;
                    b[0] = *(const uint32_t*)(br);
                    b[1] = *(const uint32_t*)(br + 8);
                    mma_bf16(oc[nt], Ap[ks], b);
                }
            }
        }
    }

    // ---- epilogue ----
    ls0 += __shfl_xor_sync(0xffffffffu, ls0, 1);
    ls0 += __shfl_xor_sync(0xffffffffu, ls0, 2);
    ls1 += __shfl_xor_sync(0xffffffffu, ls1, 1);
    ls1 += __shfl_xor_sync(0xffffffffu, ls1, 2);
    float inv0 = 1.f / ls0, inv1 = 1.f / ls1;
    float* o0 = out + (size_t)(qt * 128 + r0) * (HH * DV) + h * DV;
    float* o1 = o0 + 8 * (HH * DV);
    #pragma unroll
    for (int nt = 0; nt < 16; nt++) {
        int col = nt * 8 + 2 * tig;
        *(float2*)(o0 + col) = make_float2(oc[nt][0] * inv0, oc[nt][1] * inv0);
        *(float2*)(o1 + col) = make_float2(oc[nt][2] * inv1, oc[nt][3] * inv1);
    }
}

// ---------------------------------------------------------------------------
extern "C" void kernel_launch(void* const* d_in, const int* in_sizes, int n_in,
                              void* d_out, int out_size) {
    const float* q    = (const float*)d_in[0];   // (T, H, 192)
    const float* kc   = (const float*)d_in[1];   // (T, 512)
    const float* kpe  = (const float*)d_in[2];   // (T, 64)
    const float* wkvb = (const float*)d_in[3];   // (512, 4096)
    const float* wuv  = (const float*)d_in[4];   // (16, 512, 128)
    float* out = (float*)d_out;                  // (T, 2048)
    (void)in_sizes; (void)n_in; (void)out_size;

    cudaFuncSetAttribute(prep_mma,
        cudaFuncAttributeMaxDynamicSharedMemorySize, PREP_SMEM);
    cudaFuncSetAttribute(flash_mma,
        cudaFuncAttributeMaxDynamicSharedMemorySize, FLASH_SMEM);

    split_kc_k  <<<(TT * LORA) / 256, 256>>>(kc);
    split_q_k   <<<(HH * TT * DD) / 256, 256>>>(q);
    split_kpe_k <<<(HH * TT * ROPE) / 256, 256>>>(kpe);
    split_wbT_k <<<(HH * 128 * LORA) / 256, 256>>>(wkvb);
    split_wuvT_k<<<(HH * DV * LORA) / 256, 256>>>(wuv);

    prep_mma<<<256, 256, PREP_SMEM>>>(0);
    prep_mma<<<256, 256, PREP_SMEM>>>(1);
    flash_mma<<<256, 256, FLASH_SMEM>>>(out);
}